// round 3
// baseline (speedup 1.0000x reference)
#include <cuda_runtime.h>
#include <math.h>

// ---------------------------------------------------------------------------
// VAELoss: 0.05*KLD + 0.2*CE + 0.75*pairwise_hinge
//   m  [N,V]  f32   (N=4096, V=20000)  -> cross-entropy vs t
//   zm [N,LAT] f32, zs [N,LAT] f32     -> KLD
//   o  [U,L]  f32   (U=128, L=1024), y [U,L] i32 -> pairwise hinge
//   t  [N]    int32 OR int64 (runtime-probed; JAX x64-off downcasts)
// Single fused kernel; block-range specialization:
//   blocks [0, N)            : CE, one row each (two-pass softmax, L2 reuse)
//   blocks [N, N+U)          : pairwise hinge, one user each (smem tiles)
//   blocks [N+U, N+U+KLDB)   : KLD grid-stride
// Accumulation into __device__ double globals; last block finalizes scalar.
// ---------------------------------------------------------------------------

#define TPB 512
#define KLD_BLOCKS 8
#define L_FIXED 1024

__device__ double g_kld;
__device__ double g_ce;
__device__ double g_hinge;
__device__ unsigned long long g_cnt;
__device__ unsigned int g_done;
__device__ int g_t_is64;   // 1 if t is int64 storage, 0 if int32

__global__ void init_kernel(const int* __restrict__ t32, int N) {
    g_kld = 0.0; g_ce = 0.0; g_hinge = 0.0;
    g_cnt = 0ULL; g_done = 0u;
    // Probe: little-endian int64 values < 2^31 have all odd 32-bit words == 0.
    // Random int32 targets in [0, 20000) make that pattern vanishingly unlikely.
    int nprobe = 16;
    if (2 * nprobe > N) nprobe = N / 2;
    int all_odd_zero = 1;
    for (int i = 0; i < nprobe; ++i)
        if (t32[2 * i + 1] != 0) { all_odd_zero = 0; break; }
    g_t_is64 = all_odd_zero;
}

__device__ __forceinline__ float warpMax(float v) {
    #pragma unroll
    for (int off = 16; off > 0; off >>= 1)
        v = fmaxf(v, __shfl_xor_sync(0xFFFFFFFFu, v, off));
    return v;
}
__device__ __forceinline__ float warpSumF(float v) {
    #pragma unroll
    for (int off = 16; off > 0; off >>= 1)
        v += __shfl_xor_sync(0xFFFFFFFFu, v, off);
    return v;
}
__device__ __forceinline__ int warpSumI(int v) {
    #pragma unroll
    for (int off = 16; off > 0; off >>= 1)
        v += __shfl_xor_sync(0xFFFFFFFFu, v, off);
    return v;
}

__global__ void __launch_bounds__(TPB, 4)
loss_kernel(const float* __restrict__ m,
            const float* __restrict__ zm,
            const float* __restrict__ zs,
            const float* __restrict__ o,
            const int*   __restrict__ y,
            const int*   __restrict__ t32,
            float* __restrict__ out,
            int N, int V, int LAT, int U, int L)
{
    __shared__ float s_o[L_FIXED];
    __shared__ int   s_y[L_FIXED];
    __shared__ float s_red[16];

    const int tid  = threadIdx.x;
    const int lane = tid & 31;
    const int warp = tid >> 5;
    const int nwarps = TPB >> 5;
    const int bid  = blockIdx.x;
    const int nCE  = N;
    const int nPW  = U;

    if (bid < nCE) {
        // ------------------------- Cross-entropy row -----------------------
        const int row = bid;
        const float* base = m + (size_t)row * (size_t)V;
        const int V4 = V >> 2;
        const float4* base4 = (const float4*)base;

        // pass 1: row max
        float mx = -INFINITY;
        for (int i = tid; i < V4; i += TPB) {
            float4 v = base4[i];
            mx = fmaxf(mx, fmaxf(fmaxf(v.x, v.y), fmaxf(v.z, v.w)));
        }
        for (int i = (V4 << 2) + tid; i < V; i += TPB) mx = fmaxf(mx, base[i]);
        mx = warpMax(mx);
        if (lane == 0) s_red[warp] = mx;
        __syncthreads();
        if (warp == 0) {
            float v = (lane < nwarps) ? s_red[lane] : -INFINITY;
            v = warpMax(v);
            if (lane == 0) s_red[0] = v;
        }
        __syncthreads();
        mx = s_red[0];
        __syncthreads();

        // pass 2: sum exp(v - mx)   (row is L2-resident from pass 1)
        float ssum = 0.0f;
        for (int i = tid; i < V4; i += TPB) {
            float4 v = base4[i];
            ssum += __expf(v.x - mx) + __expf(v.y - mx)
                  + __expf(v.z - mx) + __expf(v.w - mx);
        }
        for (int i = (V4 << 2) + tid; i < V; i += TPB) ssum += __expf(base[i] - mx);
        ssum = warpSumF(ssum);
        if (lane == 0) s_red[warp] = ssum;
        __syncthreads();
        if (warp == 0) {
            float v = (lane < nwarps) ? s_red[lane] : 0.0f;
            v = warpSumF(v);
            if (lane == 0) {
                // dtype-agnostic target decode: int64 -> low word at 2*row
                int tv = g_t_is64 ? t32[2 * row] : t32[row];
                if (tv < 0) tv = 0;
                if (tv >= V) tv = V - 1;           // safety clamp (no IMA)
                float tval = base[tv];
                float nll = (mx + logf(v)) - tval; // -log_softmax at target
                atomicAdd(&g_ce, (double)nll);
            }
        }
    } else if (bid < nCE + nPW) {
        // ------------------------- Pairwise hinge for one user -------------
        const int u = bid - nCE;
        const float* orow = o + (size_t)u * (size_t)L;
        const int*   yrow = y + (size_t)u * (size_t)L;
        for (int i = tid; i < L; i += TPB) { s_o[i] = orow[i]; s_y[i] = yrow[i]; }
        __syncthreads();

        const int half = L >> 1;
        float hs = 0.0f;
        int   cnt = 0;
        // round-robin unordered-pair cover: (i, i+k mod L), k=1..half-1 all i;
        // k=half only i<half.  Hinge is symmetric in the unordered pair.
        for (int i = tid; i < L; i += TPB) {
            const int   yi = s_y[i];
            const float oi = s_o[i];
            #pragma unroll 4
            for (int k = 1; k < half; ++k) {
                int j = i + k; if (j >= L) j -= L;
                int d = yi - s_y[j];
                if (d != 0) {
                    ++cnt;
                    float oj = s_o[j];
                    float sd = (d > 0) ? (oi - oj) : (oj - oi);
                    hs += fmaxf(0.0f, 1.0f - sd);
                }
            }
            if (i < half) {
                int j = i + half;
                int d = yi - s_y[j];
                if (d != 0) {
                    ++cnt;
                    float oj = s_o[j];
                    float sd = (d > 0) ? (oi - oj) : (oj - oi);
                    hs += fmaxf(0.0f, 1.0f - sd);
                }
            }
        }
        hs = warpSumF(hs);
        cnt = warpSumI(cnt);
        __syncthreads();   // s_o/s_y reads done before smem reuse
        if (lane == 0) { s_red[warp] = hs; s_y[warp] = cnt; }
        __syncthreads();
        if (warp == 0) {
            float v = (lane < nwarps) ? s_red[lane] : 0.0f;
            int   c = (lane < nwarps) ? s_y[lane]   : 0;
            v = warpSumF(v);
            c = warpSumI(c);
            if (lane == 0) {
                atomicAdd(&g_hinge, (double)v);
                atomicAdd(&g_cnt, (unsigned long long)c);
            }
        }
    } else {
        // ------------------------- KLD ------------------------------------
        const int kb = bid - nCE - nPW;
        const int total = N * LAT;
        float acc = 0.0f;
        for (int i = kb * TPB + tid; i < total; i += KLD_BLOCKS * TPB) {
            float a = zm[i];
            float b = zs[i];
            float b2 = b * b;
            acc += a * a + b2 - __logf(b2) - 1.0f;
        }
        acc = warpSumF(acc);
        if (lane == 0) s_red[warp] = acc;
        __syncthreads();
        if (warp == 0) {
            float v = (lane < nwarps) ? s_red[lane] : 0.0f;
            v = warpSumF(v);
            if (lane == 0) atomicAdd(&g_kld, (double)v);
        }
    }

    // ------------------------- finalize (last block) -----------------------
    __syncthreads();
    if (tid == 0) {
        __threadfence();
        unsigned int done = atomicAdd(&g_done, 1u);
        if (done == gridDim.x - 1) {
            double kld = atomicAdd(&g_kld, 0.0);
            double ce  = atomicAdd(&g_ce, 0.0);
            double hg  = atomicAdd(&g_hinge, 0.0);
            unsigned long long c = atomicAdd(&g_cnt, 0ULL);
            if (c < 1ULL) c = 1ULL;
            double kld_mean = kld / (double)((size_t)N * (size_t)LAT);
            double ce_mean  = ce / (double)N;
            double pw       = hg / (double)c;
            out[0] = (float)(0.05 * kld_mean + 0.2 * ce_mean + 0.75 * pw);
        }
    }
}

extern "C" void kernel_launch(void* const* d_in, const int* in_sizes, int n_in,
                              void* d_out, int out_size)
{
    const float* m  = (const float*)d_in[0];
    const float* zm = (const float*)d_in[1];
    const float* zs = (const float*)d_in[2];
    const float* o  = (const float*)d_in[3];
    const int*   y  = (const int*)d_in[4];
    const int*   t  = (const int*)d_in[5];
    float* out = (float*)d_out;

    const int N   = in_sizes[5];           // 4096
    const int V   = in_sizes[0] / N;       // 20000
    const int LAT = in_sizes[1] / N;       // 32
    const int L   = L_FIXED;               // 1024
    const int U   = in_sizes[3] / L;       // 128

    const int grid = N + U + KLD_BLOCKS;

    init_kernel<<<1, 1>>>(t, N);
    loss_kernel<<<grid, TPB>>>(m, zm, zs, o, y, t, out, N, V, LAT, U, L);
}

// round 6
// speedup vs baseline: 2.1265x; 2.1265x over previous
#include <cuda_runtime.h>
#include <math.h>

// ---------------------------------------------------------------------------
// VAELoss = 0.05*KLD + 0.2*CE + 0.75*pairwise_hinge
//   m  [N,V] f32 (4096x20000) CE vs t;  zm,zs [N,32] KLD;
//   o [U,L] f32 (128x1024), y [U,L] i32 hinge;  t [N] i32-or-i64 (probed)
// blocks [0,N): CE one row, single-pass sumexp (fallback 2-pass if non-finite)
// blocks [N,N+U): hinge one user: bitonic sort (y,o) -> prefix sums ->
//                 per-element binary search into lower-y groups.
// blocks [N+U, +KLDB): KLD grid-stride.
// ---------------------------------------------------------------------------

#define TPB 512
#define KLD_BLOCKS 8
#define L_FIXED 1024
#define MAXG 64

__device__ double g_kld;
__device__ double g_ce;
__device__ double g_hinge;
__device__ unsigned long long g_cnt;
__device__ unsigned int g_done;
__device__ int g_t_is64;

__global__ void init_kernel(const int* __restrict__ t32, int N) {
    g_kld = 0.0; g_ce = 0.0; g_hinge = 0.0;
    g_cnt = 0ULL; g_done = 0u;
    int nprobe = 16;
    if (2 * nprobe > N) nprobe = N / 2;
    int all_odd_zero = 1;
    for (int i = 0; i < nprobe; ++i)
        if (t32[2 * i + 1] != 0) { all_odd_zero = 0; break; }
    g_t_is64 = all_odd_zero;
}

__device__ __forceinline__ float warpMax(float v) {
    #pragma unroll
    for (int off = 16; off > 0; off >>= 1)
        v = fmaxf(v, __shfl_xor_sync(0xFFFFFFFFu, v, off));
    return v;
}
__device__ __forceinline__ float warpSumF(float v) {
    #pragma unroll
    for (int off = 16; off > 0; off >>= 1)
        v += __shfl_xor_sync(0xFFFFFFFFu, v, off);
    return v;
}
__device__ __forceinline__ double warpSumD(double v) {
    #pragma unroll
    for (int off = 16; off > 0; off >>= 1)
        v += __shfl_xor_sync(0xFFFFFFFFu, v, off);
    return v;
}
__device__ __forceinline__ int warpSumI(int v) {
    #pragma unroll
    for (int off = 16; off > 0; off >>= 1)
        v += __shfl_xor_sync(0xFFFFFFFFu, v, off);
    return v;
}

// float -> order-preserving uint (and back)
__device__ __forceinline__ unsigned int f2ord(float f) {
    unsigned int u = __float_as_uint(f);
    return (u & 0x80000000u) ? ~u : (u | 0x80000000u);
}
__device__ __forceinline__ float ord2f(unsigned int u) {
    unsigned int v = (u & 0x80000000u) ? (u ^ 0x80000000u) : ~u;
    return __uint_as_float(v);
}

__global__ void __launch_bounds__(TPB, 3)
loss_kernel(const float* __restrict__ m,
            const float* __restrict__ zm,
            const float* __restrict__ zs,
            const float* __restrict__ o,
            const int*   __restrict__ y,
            const int*   __restrict__ t32,
            float* __restrict__ out,
            int N, int V, int LAT, int U, int L)
{
    __shared__ unsigned long long s_key[L_FIXED];   // sort keys (y,o)
    __shared__ float s_os[L_FIXED];                 // sorted o
    __shared__ float s_pref[L_FIXED + 1];           // exclusive prefix of s_os
    __shared__ unsigned short s_gidx[L_FIXED];      // group index per position
    __shared__ int   s_gstart[MAXG + 1];
    __shared__ float s_redf[17];
    __shared__ int   s_redi[17];

    const int tid  = threadIdx.x;
    const int lane = tid & 31;
    const int warp = tid >> 5;
    const int nwarps = TPB >> 5;
    const int bid  = blockIdx.x;
    const int nCE  = N;
    const int nPW  = U;

    if (bid < nCE) {
        // ===================== Cross-entropy (single pass) ==================
        const int row = bid;
        const float* base = m + (size_t)row * (size_t)V;
        const int V4 = V >> 2;
        const float4* base4 = (const float4*)base;

        float ssum = 0.0f;
        #pragma unroll 4
        for (int i = tid; i < V4; i += TPB) {
            float4 v = base4[i];
            ssum += __expf(v.x) + __expf(v.y) + __expf(v.z) + __expf(v.w);
        }
        for (int i = (V4 << 2) + tid; i < V; i += TPB) ssum += __expf(base[i]);
        ssum = warpSumF(ssum);
        if (lane == 0) s_redf[warp] = ssum;
        __syncthreads();
        if (warp == 0) {
            float v = (lane < nwarps) ? s_redf[lane] : 0.0f;
            v = warpSumF(v);
            if (lane == 0) s_redf[16] = logf(v);
        }
        __syncthreads();
        float logs = s_redf[16];

        if (!isfinite(logs)) {
            // -------- rare fallback: numerically-safe two-pass --------------
            float mx = -INFINITY;
            for (int i = tid; i < V4; i += TPB) {
                float4 v = base4[i];
                mx = fmaxf(mx, fmaxf(fmaxf(v.x, v.y), fmaxf(v.z, v.w)));
            }
            for (int i = (V4 << 2) + tid; i < V; i += TPB) mx = fmaxf(mx, base[i]);
            mx = warpMax(mx);
            if (lane == 0) s_redf[warp] = mx;
            __syncthreads();
            if (warp == 0) {
                float v = (lane < nwarps) ? s_redf[lane] : -INFINITY;
                v = warpMax(v);
                if (lane == 0) s_redf[16] = v;
            }
            __syncthreads();
            mx = s_redf[16];
            __syncthreads();
            float s2 = 0.0f;
            for (int i = tid; i < V4; i += TPB) {
                float4 v = base4[i];
                s2 += __expf(v.x - mx) + __expf(v.y - mx)
                    + __expf(v.z - mx) + __expf(v.w - mx);
            }
            for (int i = (V4 << 2) + tid; i < V; i += TPB) s2 += __expf(base[i] - mx);
            s2 = warpSumF(s2);
            if (lane == 0) s_redf[warp] = s2;
            __syncthreads();
            if (warp == 0) {
                float v = (lane < nwarps) ? s_redf[lane] : 0.0f;
                v = warpSumF(v);
                if (lane == 0) s_redf[16] = mx + logf(v);
            }
            __syncthreads();
            logs = s_redf[16];
        }

        if (tid == 0) {
            int tv = g_t_is64 ? t32[2 * row] : t32[row];
            if (tv < 0) tv = 0;
            if (tv >= V) tv = V - 1;
            float nll = logs - base[tv];
            atomicAdd(&g_ce, (double)nll);
        }
    } else if (bid < nCE + nPW) {
        // ===================== Pairwise hinge (sorted) ======================
        const int u = bid - nCE;
        const float* orow = o + (size_t)u * (size_t)L;
        const int*   yrow = y + (size_t)u * (size_t)L;

        // build composite keys (y asc, o asc); 2 elements per thread
        const int p0 = 2 * tid, p1 = 2 * tid + 1;
        {
            unsigned int uy0 = (unsigned int)yrow[p0] ^ 0x80000000u;
            unsigned int uy1 = (unsigned int)yrow[p1] ^ 0x80000000u;
            s_key[p0] = ((unsigned long long)uy0 << 32) | f2ord(orow[p0]);
            s_key[p1] = ((unsigned long long)uy1 << 32) | f2ord(orow[p1]);
        }
        __syncthreads();

        // bitonic sort of 1024 u64 keys, 512 threads
        for (int k = 2; k <= L_FIXED; k <<= 1) {
            for (int j = k >> 1; j > 0; j >>= 1) {
                #pragma unroll
                for (int r = 0; r < 2; ++r) {
                    int i = tid + r * TPB;
                    int ixj = i ^ j;
                    if (ixj > i) {
                        unsigned long long a = s_key[i], b = s_key[ixj];
                        bool up = ((i & k) == 0);
                        if ((a > b) == up) { s_key[i] = b; s_key[ixj] = a; }
                    }
                }
                __syncthreads();
            }
        }

        // recover sorted o, boundary flags
        unsigned long long k0 = s_key[p0], k1 = s_key[p1];
        float o0 = ord2f((unsigned int)k0);
        float o1 = ord2f((unsigned int)k1);
        s_os[p0] = o0; s_os[p1] = o1;
        unsigned int yh0 = (unsigned int)(k0 >> 32);
        unsigned int yh1 = (unsigned int)(k1 >> 32);
        int f0 = (p0 == 0) ? 1 : (yh0 != (unsigned int)(s_key[p0 - 1] >> 32));
        int f1 = (yh1 != yh0);

        // combined block scans: float (o) and int (flags), 2 contiguous/thread
        float olocal = o0 + o1;
        int   flocal = f0 + f1;
        float oincl = olocal; int fincl = flocal;
        #pragma unroll
        for (int off = 1; off < 32; off <<= 1) {
            float on = __shfl_up_sync(0xFFFFFFFFu, oincl, off);
            int   fn = __shfl_up_sync(0xFFFFFFFFu, fincl, off);
            if (lane >= off) { oincl += on; fincl += fn; }
        }
        if (lane == 31) { s_redf[warp] = oincl; s_redi[warp] = fincl; }
        __syncthreads();
        if (warp == 0) {
            float ov = (lane < nwarps) ? s_redf[lane] : 0.0f;
            int   fv = (lane < nwarps) ? s_redi[lane] : 0;
            float oi2 = ov; int fi2 = fv;
            #pragma unroll
            for (int off = 1; off < 16; off <<= 1) {
                float on = __shfl_up_sync(0xFFFFFFFFu, oi2, off);
                int   fn = __shfl_up_sync(0xFFFFFFFFu, fi2, off);
                if (lane >= off) { oi2 += on; fi2 += fn; }
            }
            if (lane < nwarps) { s_redf[lane] = oi2 - ov; s_redi[lane] = fi2 - fv; } // exclusive
        }
        __syncthreads();
        float oexcl = s_redf[warp] + (oincl - olocal);
        int   fexcl = s_redi[warp] + (fincl - flocal);
        __syncthreads();

        s_pref[p0] = oexcl;
        s_pref[p1] = oexcl + o0;
        if (p1 == L_FIXED - 1) s_pref[L_FIXED] = oexcl + o0 + o1;
        int g0 = fexcl + f0 - 1;
        int g1 = fexcl + f0 + f1 - 1;
        s_gidx[p0] = (unsigned short)g0;
        s_gidx[p1] = (unsigned short)g1;
        if (f0 && g0 < MAXG) s_gstart[g0] = p0;
        if (f1 && g1 < MAXG) s_gstart[g1] = p1;
        __syncthreads();

        int ngroups = (int)s_gidx[L_FIXED - 1] + 1;
        if (tid == 0 && ngroups <= MAXG) s_gstart[ngroups] = L_FIXED;
        __syncthreads();

        double hs = 0.0;
        int    vc = 0;
        if (ngroups <= MAXG) {
            #pragma unroll
            for (int r = 0; r < 2; ++r) {
                int p = 2 * tid + r;
                int g = (int)s_gidx[p];
                float oi = s_os[p];
                float thr = oi - 1.0f;
                vc += (g > 0) ? s_gstart[g] : 0;   // all lower-y elements
                for (int gb = 0; gb < g; ++gb) {
                    int lo = s_gstart[gb];
                    const int end = s_gstart[gb + 1];
                    int hi = end;
                    while (lo < hi) {
                        int mid = (lo + hi) >> 1;
                        if (s_os[mid] > thr) hi = mid; else lo = mid + 1;
                    }
                    int cnt = end - lo;
                    if (cnt > 0)
                        hs += (double)((float)cnt * (1.0f - oi)
                                       + (s_pref[end] - s_pref[lo]));
                }
            }
        } else {
            // fallback: brute force over sorted arrays (never for this data)
            for (int p = tid; p < L_FIXED; p += TPB) {
                int gp = (int)s_gidx[p];
                float op = s_os[p];
                for (int q = p + 1; q < L_FIXED; ++q) {
                    if ((int)s_gidx[q] > gp) {
                        ++vc;
                        hs += (double)fmaxf(0.0f, 1.0f - (s_os[q] - op));
                    }
                }
            }
        }

        hs = warpSumD(hs);
        vc = warpSumI(vc);
        __syncthreads();
        if (lane == 0) { ((double*)s_key)[warp] = hs; s_redi[warp] = vc; }
        __syncthreads();
        if (warp == 0) {
            double v = (lane < nwarps) ? ((double*)s_key)[lane] : 0.0;
            int    c = (lane < nwarps) ? s_redi[lane] : 0;
            v = warpSumD(v);
            c = warpSumI(c);
            if (lane == 0) {
                atomicAdd(&g_hinge, v);
                atomicAdd(&g_cnt, (unsigned long long)c);
            }
        }
    } else {
        // ===================== KLD =========================================
        const int kb = bid - nCE - nPW;
        const int total = N * LAT;
        float acc = 0.0f;
        for (int i = kb * TPB + tid; i < total; i += KLD_BLOCKS * TPB) {
            float a = zm[i];
            float b = zs[i];
            float b2 = b * b;
            acc += a * a + b2 - __logf(b2) - 1.0f;
        }
        acc = warpSumF(acc);
        if (lane == 0) s_redf[warp] = acc;
        __syncthreads();
        if (warp == 0) {
            float v = (lane < nwarps) ? s_redf[lane] : 0.0f;
            v = warpSumF(v);
            if (lane == 0) atomicAdd(&g_kld, (double)v);
        }
    }

    // ===================== finalize (last block) ============================
    __syncthreads();
    if (tid == 0) {
        __threadfence();
        unsigned int done = atomicAdd(&g_done, 1u);
        if (done == gridDim.x - 1) {
            double kld = atomicAdd(&g_kld, 0.0);
            double ce  = atomicAdd(&g_ce, 0.0);
            double hg  = atomicAdd(&g_hinge, 0.0);
            unsigned long long c = atomicAdd(&g_cnt, 0ULL);
            if (c < 1ULL) c = 1ULL;
            double kld_mean = kld / (double)((size_t)N * (size_t)LAT);
            double ce_mean  = ce / (double)N;
            double pw       = hg / (double)c;
            out[0] = (float)(0.05 * kld_mean + 0.2 * ce_mean + 0.75 * pw);
        }
    }
}

extern "C" void kernel_launch(void* const* d_in, const int* in_sizes, int n_in,
                              void* d_out, int out_size)
{
    const float* m  = (const float*)d_in[0];
    const float* zm = (const float*)d_in[1];
    const float* zs = (const float*)d_in[2];
    const float* o  = (const float*)d_in[3];
    const int*   y  = (const int*)d_in[4];
    const int*   t  = (const int*)d_in[5];
    float* out = (float*)d_out;

    const int N   = in_sizes[5];           // 4096
    const int V   = in_sizes[0] / N;       // 20000
    const int LAT = in_sizes[1] / N;       // 32
    const int L   = L_FIXED;               // 1024
    const int U   = in_sizes[3] / L;       // 128

    const int grid = N + U + KLD_BLOCKS;

    init_kernel<<<1, 1>>>(t, N);
    loss_kernel<<<grid, TPB>>>(m, zm, zs, o, y, t, out, N, V, LAT, U, L);
}

// round 7
// speedup vs baseline: 2.9048x; 1.3660x over previous
#include <cuda_runtime.h>
#include <math.h>

// ---------------------------------------------------------------------------
// VAELoss = 0.05*KLD + 0.2*CE + 0.75*pairwise_hinge
//   m  [N,V] f32 (4096x20000) CE vs t;  zm,zs [N,32] KLD;
//   o [U,L] f32 (128x1024), y [U,L] i32 hinge;  t [N] i32-or-i64 (probed)
// Block layout (hinge/KLD FIRST so they run in wave 0, hidden under CE):
//   [0, U)               : hinge, one user per block (sort+prefix+binsearch)
//   [U, U+KLDB)          : KLD grid-stride
//   [U+KLDB, U+KLDB+N)   : CE one row, single-pass sumexp, 4 accumulators,
//                          batched float4 loads (MLP>=4/thread)
// ---------------------------------------------------------------------------

#define TPB 512
#define KLD_BLOCKS 8
#define L_FIXED 1024
#define MAXG 64

__device__ double g_kld;
__device__ double g_ce;
__device__ double g_hinge;
__device__ unsigned long long g_cnt;
__device__ unsigned int g_done;
__device__ int g_t_is64;

__global__ void init_kernel(const int* __restrict__ t32, int N) {
    g_kld = 0.0; g_ce = 0.0; g_hinge = 0.0;
    g_cnt = 0ULL; g_done = 0u;
    int nprobe = 16;
    if (2 * nprobe > N) nprobe = N / 2;
    int all_odd_zero = 1;
    for (int i = 0; i < nprobe; ++i)
        if (t32[2 * i + 1] != 0) { all_odd_zero = 0; break; }
    g_t_is64 = all_odd_zero;
}

__device__ __forceinline__ float warpMax(float v) {
    #pragma unroll
    for (int off = 16; off > 0; off >>= 1)
        v = fmaxf(v, __shfl_xor_sync(0xFFFFFFFFu, v, off));
    return v;
}
__device__ __forceinline__ float warpSumF(float v) {
    #pragma unroll
    for (int off = 16; off > 0; off >>= 1)
        v += __shfl_xor_sync(0xFFFFFFFFu, v, off);
    return v;
}
__device__ __forceinline__ double warpSumD(double v) {
    #pragma unroll
    for (int off = 16; off > 0; off >>= 1)
        v += __shfl_xor_sync(0xFFFFFFFFu, v, off);
    return v;
}
__device__ __forceinline__ int warpSumI(int v) {
    #pragma unroll
    for (int off = 16; off > 0; off >>= 1)
        v += __shfl_xor_sync(0xFFFFFFFFu, v, off);
    return v;
}

__device__ __forceinline__ unsigned int f2ord(float f) {
    unsigned int u = __float_as_uint(f);
    return (u & 0x80000000u) ? ~u : (u | 0x80000000u);
}
__device__ __forceinline__ float ord2f(unsigned int u) {
    unsigned int v = (u & 0x80000000u) ? (u ^ 0x80000000u) : ~u;
    return __uint_as_float(v);
}

__device__ __forceinline__ float exp4(float4 v) {
    return __expf(v.x) + __expf(v.y) + __expf(v.z) + __expf(v.w);
}

__global__ void __launch_bounds__(TPB, 4)
loss_kernel(const float* __restrict__ m,
            const float* __restrict__ zm,
            const float* __restrict__ zs,
            const float* __restrict__ o,
            const int*   __restrict__ y,
            const int*   __restrict__ t32,
            float* __restrict__ out,
            int N, int V, int LAT, int U, int L)
{
    __shared__ unsigned long long s_key[L_FIXED];   // sort keys (y,o)
    __shared__ float s_os[L_FIXED];                 // sorted o
    __shared__ float s_pref[L_FIXED + 1];           // exclusive prefix of s_os
    __shared__ unsigned short s_gidx[L_FIXED];      // group index per position
    __shared__ int   s_gstart[MAXG + 1];
    __shared__ float s_redf[17];
    __shared__ int   s_redi[17];

    const int tid  = threadIdx.x;
    const int lane = tid & 31;
    const int warp = tid >> 5;
    const int nwarps = TPB >> 5;
    const int bid  = blockIdx.x;
    const int nPW  = U;                 // hinge blocks first (wave 0)
    const int nKB  = KLD_BLOCKS;

    if (bid >= nPW + nKB) {
        // ===================== Cross-entropy (single pass) ==================
        const int row = bid - nPW - nKB;
        const float* base = m + (size_t)row * (size_t)V;
        const int V4 = V >> 2;
        const float4* base4 = (const float4*)base;

        float a0 = 0.0f, a1 = 0.0f, a2 = 0.0f, a3 = 0.0f;
        int i = tid;
        for (; i + 3 * TPB < V4; i += 4 * TPB) {
            float4 v0 = base4[i];
            float4 v1 = base4[i + TPB];
            float4 v2 = base4[i + 2 * TPB];
            float4 v3 = base4[i + 3 * TPB];
            a0 += exp4(v0);
            a1 += exp4(v1);
            a2 += exp4(v2);
            a3 += exp4(v3);
        }
        for (; i < V4; i += TPB) a0 += exp4(base4[i]);
        for (int j = (V4 << 2) + tid; j < V; j += TPB) a0 += __expf(base[j]);
        float ssum = (a0 + a1) + (a2 + a3);

        ssum = warpSumF(ssum);
        if (lane == 0) s_redf[warp] = ssum;
        __syncthreads();
        if (warp == 0) {
            float v = (lane < nwarps) ? s_redf[lane] : 0.0f;
            v = warpSumF(v);
            if (lane == 0) s_redf[16] = logf(v);
        }
        __syncthreads();
        float logs = s_redf[16];

        if (!isfinite(logs)) {
            // -------- rare fallback: numerically-safe two-pass --------------
            float mx = -INFINITY;
            for (int k = tid; k < V4; k += TPB) {
                float4 v = base4[k];
                mx = fmaxf(mx, fmaxf(fmaxf(v.x, v.y), fmaxf(v.z, v.w)));
            }
            for (int k = (V4 << 2) + tid; k < V; k += TPB) mx = fmaxf(mx, base[k]);
            mx = warpMax(mx);
            if (lane == 0) s_redf[warp] = mx;
            __syncthreads();
            if (warp == 0) {
                float v = (lane < nwarps) ? s_redf[lane] : -INFINITY;
                v = warpMax(v);
                if (lane == 0) s_redf[16] = v;
            }
            __syncthreads();
            mx = s_redf[16];
            __syncthreads();
            float s2 = 0.0f;
            for (int k = tid; k < V4; k += TPB) {
                float4 v = base4[k];
                s2 += __expf(v.x - mx) + __expf(v.y - mx)
                    + __expf(v.z - mx) + __expf(v.w - mx);
            }
            for (int k = (V4 << 2) + tid; k < V; k += TPB) s2 += __expf(base[k] - mx);
            s2 = warpSumF(s2);
            if (lane == 0) s_redf[warp] = s2;
            __syncthreads();
            if (warp == 0) {
                float v = (lane < nwarps) ? s_redf[lane] : 0.0f;
                v = warpSumF(v);
                if (lane == 0) s_redf[16] = mx + logf(v);
            }
            __syncthreads();
            logs = s_redf[16];
        }

        if (tid == 0) {
            int tv = g_t_is64 ? t32[2 * row] : t32[row];
            if (tv < 0) tv = 0;
            if (tv >= V) tv = V - 1;
            float nll = logs - base[tv];
            atomicAdd(&g_ce, (double)nll);
        }
    } else if (bid < nPW) {
        // ===================== Pairwise hinge (sorted) ======================
        const int u = bid;
        const float* orow = o + (size_t)u * (size_t)L;
        const int*   yrow = y + (size_t)u * (size_t)L;

        // build composite keys (y asc, o asc); 2 elements per thread
        const int p0 = 2 * tid, p1 = 2 * tid + 1;
        {
            unsigned int uy0 = (unsigned int)yrow[p0] ^ 0x80000000u;
            unsigned int uy1 = (unsigned int)yrow[p1] ^ 0x80000000u;
            s_key[p0] = ((unsigned long long)uy0 << 32) | f2ord(orow[p0]);
            s_key[p1] = ((unsigned long long)uy1 << 32) | f2ord(orow[p1]);
        }
        __syncthreads();

        // bitonic sort of 1024 u64 keys, 512 threads
        for (int k = 2; k <= L_FIXED; k <<= 1) {
            for (int j = k >> 1; j > 0; j >>= 1) {
                #pragma unroll
                for (int r = 0; r < 2; ++r) {
                    int i = tid + r * TPB;
                    int ixj = i ^ j;
                    if (ixj > i) {
                        unsigned long long a = s_key[i], b = s_key[ixj];
                        bool up = ((i & k) == 0);
                        if ((a > b) == up) { s_key[i] = b; s_key[ixj] = a; }
                    }
                }
                __syncthreads();
            }
        }

        // recover sorted o, boundary flags
        unsigned long long k0 = s_key[p0], k1 = s_key[p1];
        float o0 = ord2f((unsigned int)k0);
        float o1 = ord2f((unsigned int)k1);
        s_os[p0] = o0; s_os[p1] = o1;
        unsigned int yh0 = (unsigned int)(k0 >> 32);
        unsigned int yh1 = (unsigned int)(k1 >> 32);
        int f0 = (p0 == 0) ? 1 : (yh0 != (unsigned int)(s_key[p0 - 1] >> 32));
        int f1 = (yh1 != yh0);

        // combined block scans: float (o) and int (flags), 2 contiguous/thread
        float olocal = o0 + o1;
        int   flocal = f0 + f1;
        float oincl = olocal; int fincl = flocal;
        #pragma unroll
        for (int off = 1; off < 32; off <<= 1) {
            float on = __shfl_up_sync(0xFFFFFFFFu, oincl, off);
            int   fn = __shfl_up_sync(0xFFFFFFFFu, fincl, off);
            if (lane >= off) { oincl += on; fincl += fn; }
        }
        if (lane == 31) { s_redf[warp] = oincl; s_redi[warp] = fincl; }
        __syncthreads();
        if (warp == 0) {
            float ov = (lane < nwarps) ? s_redf[lane] : 0.0f;
            int   fv = (lane < nwarps) ? s_redi[lane] : 0;
            float oi2 = ov; int fi2 = fv;
            #pragma unroll
            for (int off = 1; off < 16; off <<= 1) {
                float on = __shfl_up_sync(0xFFFFFFFFu, oi2, off);
                int   fn = __shfl_up_sync(0xFFFFFFFFu, fi2, off);
                if (lane >= off) { oi2 += on; fi2 += fn; }
            }
            if (lane < nwarps) { s_redf[lane] = oi2 - ov; s_redi[lane] = fi2 - fv; } // exclusive
        }
        __syncthreads();
        float oexcl = s_redf[warp] + (oincl - olocal);
        int   fexcl = s_redi[warp] + (fincl - flocal);
        __syncthreads();

        s_pref[p0] = oexcl;
        s_pref[p1] = oexcl + o0;
        if (p1 == L_FIXED - 1) s_pref[L_FIXED] = oexcl + o0 + o1;
        int g0 = fexcl + f0 - 1;
        int g1 = fexcl + f0 + f1 - 1;
        s_gidx[p0] = (unsigned short)g0;
        s_gidx[p1] = (unsigned short)g1;
        if (f0 && g0 < MAXG) s_gstart[g0] = p0;
        if (f1 && g1 < MAXG) s_gstart[g1] = p1;
        __syncthreads();

        int ngroups = (int)s_gidx[L_FIXED - 1] + 1;
        if (tid == 0 && ngroups <= MAXG) s_gstart[ngroups] = L_FIXED;
        __syncthreads();

        double hs = 0.0;
        int    vc = 0;
        if (ngroups <= MAXG) {
            #pragma unroll
            for (int r = 0; r < 2; ++r) {
                int p = 2 * tid + r;
                int g = (int)s_gidx[p];
                float oi = s_os[p];
                float thr = oi - 1.0f;
                vc += (g > 0) ? s_gstart[g] : 0;   // all lower-y elements
                for (int gb = 0; gb < g; ++gb) {
                    int lo = s_gstart[gb];
                    const int end = s_gstart[gb + 1];
                    int hi = end;
                    while (lo < hi) {
                        int mid = (lo + hi) >> 1;
                        if (s_os[mid] > thr) hi = mid; else lo = mid + 1;
                    }
                    int cnt = end - lo;
                    if (cnt > 0)
                        hs += (double)((float)cnt * (1.0f - oi)
                                       + (s_pref[end] - s_pref[lo]));
                }
            }
        } else {
            // fallback: brute force over sorted arrays (never for this data)
            for (int p = tid; p < L_FIXED; p += TPB) {
                int gp = (int)s_gidx[p];
                float op = s_os[p];
                for (int q = p + 1; q < L_FIXED; ++q) {
                    if ((int)s_gidx[q] > gp) {
                        ++vc;
                        hs += (double)fmaxf(0.0f, 1.0f - (s_os[q] - op));
                    }
                }
            }
        }

        hs = warpSumD(hs);
        vc = warpSumI(vc);
        __syncthreads();
        if (lane == 0) { ((double*)s_key)[warp] = hs; s_redi[warp] = vc; }
        __syncthreads();
        if (warp == 0) {
            double v = (lane < nwarps) ? ((double*)s_key)[lane] : 0.0;
            int    c = (lane < nwarps) ? s_redi[lane] : 0;
            v = warpSumD(v);
            c = warpSumI(c);
            if (lane == 0) {
                atomicAdd(&g_hinge, v);
                atomicAdd(&g_cnt, (unsigned long long)c);
            }
        }
    } else {
        // ===================== KLD =========================================
        const int kb = bid - nPW;
        const int total = N * LAT;
        float acc = 0.0f;
        for (int i = kb * TPB + tid; i < total; i += KLD_BLOCKS * TPB) {
            float a = zm[i];
            float b = zs[i];
            float b2 = b * b;
            acc += a * a + b2 - __logf(b2) - 1.0f;
        }
        acc = warpSumF(acc);
        if (lane == 0) s_redf[warp] = acc;
        __syncthreads();
        if (warp == 0) {
            float v = (lane < nwarps) ? s_redf[lane] : 0.0f;
            v = warpSumF(v);
            if (lane == 0) atomicAdd(&g_kld, (double)v);
        }
    }

    // ===================== finalize (last block) ============================
    __syncthreads();
    if (tid == 0) {
        __threadfence();
        unsigned int done = atomicAdd(&g_done, 1u);
        if (done == gridDim.x - 1) {
            double kld = atomicAdd(&g_kld, 0.0);
            double ce  = atomicAdd(&g_ce, 0.0);
            double hg  = atomicAdd(&g_hinge, 0.0);
            unsigned long long c = atomicAdd(&g_cnt, 0ULL);
            if (c < 1ULL) c = 1ULL;
            double kld_mean = kld / (double)((size_t)N * (size_t)LAT);
            double ce_mean  = ce / (double)N;
            double pw       = hg / (double)c;
            out[0] = (float)(0.05 * kld_mean + 0.2 * ce_mean + 0.75 * pw);
        }
    }
}

extern "C" void kernel_launch(void* const* d_in, const int* in_sizes, int n_in,
                              void* d_out, int out_size)
{
    const float* m  = (const float*)d_in[0];
    const float* zm = (const float*)d_in[1];
    const float* zs = (const float*)d_in[2];
    const float* o  = (const float*)d_in[3];
    const int*   y  = (const int*)d_in[4];
    const int*   t  = (const int*)d_in[5];
    float* out = (float*)d_out;

    const int N   = in_sizes[5];           // 4096
    const int V   = in_sizes[0] / N;       // 20000
    const int LAT = in_sizes[1] / N;       // 32
    const int L   = L_FIXED;               // 1024
    const int U   = in_sizes[3] / L;       // 128

    const int grid = U + KLD_BLOCKS + N;

    init_kernel<<<1, 1>>>(t, N);
    loss_kernel<<<grid, TPB>>>(m, zm, zs, o, y, t, out, N, V, LAT, U, L);
}

// round 9
// speedup vs baseline: 3.0984x; 1.0666x over previous
#include <cuda_runtime.h>
#include <math.h>

// ---------------------------------------------------------------------------
// VAELoss = 0.05*KLD + 0.2*CE + 0.75*pairwise_hinge
//   m  [N,V] f32 (4096x20000) CE vs t;  zm,zs [N,32] KLD;
//   o [U,L] f32 (128x1024), y [U,L] i32 hinge;  t [N] i32-or-i64 (probed)
// Near-single-wave persistent layout (1160 blocks, all resident):
//   [0, U)               : hinge, one user per block (sort+prefix+binsearch)
//   [U, U+KLDB)          : KLD grid-stride
//   [U+KLDB, +NCEB)      : CE, each block processes N/NCEB = 4 rows
//                          (single-pass sumexp, 4 accumulators, batched float4)
// ---------------------------------------------------------------------------

#define TPB 512
#define KLD_BLOCKS 8
#define NCE_BLOCKS 1024
#define L_FIXED 1024
#define MAXG 64

__device__ double g_kld;
__device__ double g_ce;
__device__ double g_hinge;
__device__ unsigned long long g_cnt;
__device__ unsigned int g_done;
__device__ int g_t_is64;

__global__ void init_kernel(const int* __restrict__ t32, int N) {
    g_kld = 0.0; g_ce = 0.0; g_hinge = 0.0;
    g_cnt = 0ULL; g_done = 0u;
    int nprobe = 16;
    if (2 * nprobe > N) nprobe = N / 2;
    int all_odd_zero = 1;
    for (int i = 0; i < nprobe; ++i)
        if (t32[2 * i + 1] != 0) { all_odd_zero = 0; break; }
    g_t_is64 = all_odd_zero;
}

__device__ __forceinline__ float warpMax(float v) {
    #pragma unroll
    for (int off = 16; off > 0; off >>= 1)
        v = fmaxf(v, __shfl_xor_sync(0xFFFFFFFFu, v, off));
    return v;
}
__device__ __forceinline__ float warpSumF(float v) {
    #pragma unroll
    for (int off = 16; off > 0; off >>= 1)
        v += __shfl_xor_sync(0xFFFFFFFFu, v, off);
    return v;
}
__device__ __forceinline__ double warpSumD(double v) {
    #pragma unroll
    for (int off = 16; off > 0; off >>= 1)
        v += __shfl_xor_sync(0xFFFFFFFFu, v, off);
    return v;
}
__device__ __forceinline__ int warpSumI(int v) {
    #pragma unroll
    for (int off = 16; off > 0; off >>= 1)
        v += __shfl_xor_sync(0xFFFFFFFFu, v, off);
    return v;
}

__device__ __forceinline__ unsigned int f2ord(float f) {
    unsigned int u = __float_as_uint(f);
    return (u & 0x80000000u) ? ~u : (u | 0x80000000u);
}
__device__ __forceinline__ float ord2f(unsigned int u) {
    unsigned int v = (u & 0x80000000u) ? (u ^ 0x80000000u) : ~u;
    return __uint_as_float(v);
}

__device__ __forceinline__ float exp4(float4 v) {
    return (__expf(v.x) + __expf(v.y)) + (__expf(v.z) + __expf(v.w));
}

__global__ void __launch_bounds__(TPB, 4)
loss_kernel(const float* __restrict__ m,
            const float* __restrict__ zm,
            const float* __restrict__ zs,
            const float* __restrict__ o,
            const int*   __restrict__ y,
            const int*   __restrict__ t32,
            float* __restrict__ out,
            int N, int V, int LAT, int U, int L)
{
    __shared__ unsigned long long s_key[L_FIXED];   // sort keys (y,o)
    __shared__ float s_os[L_FIXED];                 // sorted o
    __shared__ float s_pref[L_FIXED + 1];           // exclusive prefix of s_os
    __shared__ unsigned short s_gidx[L_FIXED];      // group index per position
    __shared__ int   s_gstart[MAXG + 1];
    __shared__ float s_redf[17];
    __shared__ int   s_redi[17];

    const int tid  = threadIdx.x;
    const int lane = tid & 31;
    const int warp = tid >> 5;
    const int nwarps = TPB >> 5;
    const int bid  = blockIdx.x;
    const int nPW  = U;                 // hinge blocks first (wave 0)
    const int nKB  = KLD_BLOCKS;

    if (bid >= nPW + nKB) {
        // ========== Cross-entropy: this block handles rows ceBid+k*NCEB =====
        const int ceBid = bid - nPW - nKB;
        const int V4 = V >> 2;

        for (int row = ceBid; row < N; row += NCE_BLOCKS) {
            const float* base = m + (size_t)row * (size_t)V;
            const float4* base4 = (const float4*)base;

            float a0 = 0.0f, a1 = 0.0f, a2 = 0.0f, a3 = 0.0f;
            int i = tid;
            for (; i + 3 * TPB < V4; i += 4 * TPB) {
                float4 v0 = base4[i];
                float4 v1 = base4[i + TPB];
                float4 v2 = base4[i + 2 * TPB];
                float4 v3 = base4[i + 3 * TPB];
                a0 += exp4(v0);
                a1 += exp4(v1);
                a2 += exp4(v2);
                a3 += exp4(v3);
            }
            for (; i < V4; i += TPB) a0 += exp4(base4[i]);
            for (int j = (V4 << 2) + tid; j < V; j += TPB) a0 += __expf(base[j]);
            float ssum = (a0 + a1) + (a2 + a3);

            ssum = warpSumF(ssum);
            if (lane == 0) s_redf[warp] = ssum;
            __syncthreads();
            if (warp == 0) {
                float v = (lane < nwarps) ? s_redf[lane] : 0.0f;
                v = warpSumF(v);
                if (lane == 0) s_redf[16] = logf(v);
            }
            __syncthreads();
            float logs = s_redf[16];
            __syncthreads();   // s_redf reusable next row iteration

            if (!isfinite(logs)) {
                // -------- rare fallback: numerically-safe two-pass ----------
                float mx = -INFINITY;
                for (int k = tid; k < V4; k += TPB) {
                    float4 v = base4[k];
                    mx = fmaxf(mx, fmaxf(fmaxf(v.x, v.y), fmaxf(v.z, v.w)));
                }
                for (int k = (V4 << 2) + tid; k < V; k += TPB) mx = fmaxf(mx, base[k]);
                mx = warpMax(mx);
                if (lane == 0) s_redf[warp] = mx;
                __syncthreads();
                if (warp == 0) {
                    float v = (lane < nwarps) ? s_redf[lane] : -INFINITY;
                    v = warpMax(v);
                    if (lane == 0) s_redf[16] = v;
                }
                __syncthreads();
                mx = s_redf[16];
                __syncthreads();
                float s2 = 0.0f;
                for (int k = tid; k < V4; k += TPB) {
                    float4 v = base4[k];
                    s2 += __expf(v.x - mx) + __expf(v.y - mx)
                        + __expf(v.z - mx) + __expf(v.w - mx);
                }
                for (int k = (V4 << 2) + tid; k < V; k += TPB) s2 += __expf(base[k] - mx);
                s2 = warpSumF(s2);
                if (lane == 0) s_redf[warp] = s2;
                __syncthreads();
                if (warp == 0) {
                    float v = (lane < nwarps) ? s_redf[lane] : 0.0f;
                    v = warpSumF(v);
                    if (lane == 0) s_redf[16] = mx + logf(v);
                }
                __syncthreads();
                logs = s_redf[16];
                __syncthreads();
            }

            if (tid == 0) {
                int tv = g_t_is64 ? t32[2 * row] : t32[row];
                if (tv < 0) tv = 0;
                if (tv >= V) tv = V - 1;
                float nll = logs - base[tv];
                atomicAdd(&g_ce, (double)nll);
            }
        }
    } else if (bid < nPW) {
        // ===================== Pairwise hinge (sorted) ======================
        const int u = bid;
        const float* orow = o + (size_t)u * (size_t)L;
        const int*   yrow = y + (size_t)u * (size_t)L;

        // build composite keys (y asc, o asc); 2 elements per thread
        const int p0 = 2 * tid, p1 = 2 * tid + 1;
        {
            unsigned int uy0 = (unsigned int)yrow[p0] ^ 0x80000000u;
            unsigned int uy1 = (unsigned int)yrow[p1] ^ 0x80000000u;
            s_key[p0] = ((unsigned long long)uy0 << 32) | f2ord(orow[p0]);
            s_key[p1] = ((unsigned long long)uy1 << 32) | f2ord(orow[p1]);
        }
        __syncthreads();

        // bitonic sort of 1024 u64 keys, 512 threads
        for (int k = 2; k <= L_FIXED; k <<= 1) {
            for (int j = k >> 1; j > 0; j >>= 1) {
                #pragma unroll
                for (int r = 0; r < 2; ++r) {
                    int i = tid + r * TPB;
                    int ixj = i ^ j;
                    if (ixj > i) {
                        unsigned long long a = s_key[i], b = s_key[ixj];
                        bool up = ((i & k) == 0);
                        if ((a > b) == up) { s_key[i] = b; s_key[ixj] = a; }
                    }
                }
                __syncthreads();
            }
        }

        // recover sorted o, boundary flags
        unsigned long long k0 = s_key[p0], k1 = s_key[p1];
        float o0 = ord2f((unsigned int)k0);
        float o1 = ord2f((unsigned int)k1);
        s_os[p0] = o0; s_os[p1] = o1;
        unsigned int yh0 = (unsigned int)(k0 >> 32);
        unsigned int yh1 = (unsigned int)(k1 >> 32);
        int f0 = (p0 == 0) ? 1 : (yh0 != (unsigned int)(s_key[p0 - 1] >> 32));
        int f1 = (yh1 != yh0);

        // combined block scans: float (o) and int (flags), 2 contiguous/thread
        float olocal = o0 + o1;
        int   flocal = f0 + f1;
        float oincl = olocal; int fincl = flocal;
        #pragma unroll
        for (int off = 1; off < 32; off <<= 1) {
            float on = __shfl_up_sync(0xFFFFFFFFu, oincl, off);
            int   fn = __shfl_up_sync(0xFFFFFFFFu, fincl, off);
            if (lane >= off) { oincl += on; fincl += fn; }
        }
        if (lane == 31) { s_redf[warp] = oincl; s_redi[warp] = fincl; }
        __syncthreads();
        if (warp == 0) {
            float ov = (lane < nwarps) ? s_redf[lane] : 0.0f;
            int   fv = (lane < nwarps) ? s_redi[lane] : 0;
            float oi2 = ov; int fi2 = fv;
            #pragma unroll
            for (int off = 1; off < 16; off <<= 1) {
                float on = __shfl_up_sync(0xFFFFFFFFu, oi2, off);
                int   fn = __shfl_up_sync(0xFFFFFFFFu, fi2, off);
                if (lane >= off) { oi2 += on; fi2 += fn; }
            }
            if (lane < nwarps) { s_redf[lane] = oi2 - ov; s_redi[lane] = fi2 - fv; } // exclusive
        }
        __syncthreads();
        float oexcl = s_redf[warp] + (oincl - olocal);
        int   fexcl = s_redi[warp] + (fincl - flocal);
        __syncthreads();

        s_pref[p0] = oexcl;
        s_pref[p1] = oexcl + o0;
        if (p1 == L_FIXED - 1) s_pref[L_FIXED] = oexcl + o0 + o1;
        int g0 = fexcl + f0 - 1;
        int g1 = fexcl + f0 + f1 - 1;
        s_gidx[p0] = (unsigned short)g0;
        s_gidx[p1] = (unsigned short)g1;
        if (f0 && g0 < MAXG) s_gstart[g0] = p0;
        if (f1 && g1 < MAXG) s_gstart[g1] = p1;
        __syncthreads();

        int ngroups = (int)s_gidx[L_FIXED - 1] + 1;
        if (tid == 0 && ngroups <= MAXG) s_gstart[ngroups] = L_FIXED;
        __syncthreads();

        double hs = 0.0;
        int    vc = 0;
        if (ngroups <= MAXG) {
            #pragma unroll
            for (int r = 0; r < 2; ++r) {
                int p = 2 * tid + r;
                int g = (int)s_gidx[p];
                float oi = s_os[p];
                float thr = oi - 1.0f;
                vc += (g > 0) ? s_gstart[g] : 0;   // all lower-y elements
                for (int gb = 0; gb < g; ++gb) {
                    int lo = s_gstart[gb];
                    const int end = s_gstart[gb + 1];
                    int hi = end;
                    while (lo < hi) {
                        int mid = (lo + hi) >> 1;
                        if (s_os[mid] > thr) hi = mid; else lo = mid + 1;
                    }
                    int cnt = end - lo;
                    if (cnt > 0)
                        hs += (double)((float)cnt * (1.0f - oi)
                                       + (s_pref[end] - s_pref[lo]));
                }
            }
        } else {
            // fallback: brute force over sorted arrays (never for this data)
            for (int p = tid; p < L_FIXED; p += TPB) {
                int gp = (int)s_gidx[p];
                float op = s_os[p];
                for (int q = p + 1; q < L_FIXED; ++q) {
                    if ((int)s_gidx[q] > gp) {
                        ++vc;
                        hs += (double)fmaxf(0.0f, 1.0f - (s_os[q] - op));
                    }
                }
            }
        }

        hs = warpSumD(hs);
        vc = warpSumI(vc);
        __syncthreads();
        if (lane == 0) { ((double*)s_key)[warp] = hs; s_redi[warp] = vc; }
        __syncthreads();
        if (warp == 0) {
            double v = (lane < nwarps) ? ((double*)s_key)[lane] : 0.0;
            int    c = (lane < nwarps) ? s_redi[lane] : 0;
            v = warpSumD(v);
            c = warpSumI(c);
            if (lane == 0) {
                atomicAdd(&g_hinge, v);
                atomicAdd(&g_cnt, (unsigned long long)c);
            }
        }
    } else {
        // ===================== KLD =========================================
        const int kb = bid - nPW;
        const int total = N * LAT;
        float acc = 0.0f;
        for (int i = kb * TPB + tid; i < total; i += KLD_BLOCKS * TPB) {
            float a = zm[i];
            float b = zs[i];
            float b2 = b * b;
            acc += a * a + b2 - __logf(b2) - 1.0f;
        }
        acc = warpSumF(acc);
        if (lane == 0) s_redf[warp] = acc;
        __syncthreads();
        if (warp == 0) {
            float v = (lane < nwarps) ? s_redf[lane] : 0.0f;
            v = warpSumF(v);
            if (lane == 0) atomicAdd(&g_kld, (double)v);
        }
    }

    // ===================== finalize (last block) ============================
    __syncthreads();
    if (tid == 0) {
        __threadfence();
        unsigned int done = atomicAdd(&g_done, 1u);
        if (done == gridDim.x - 1) {
            double kld = atomicAdd(&g_kld, 0.0);
            double ce  = atomicAdd(&g_ce, 0.0);
            double hg  = atomicAdd(&g_hinge, 0.0);
            unsigned long long c = atomicAdd(&g_cnt, 0ULL);
            if (c < 1ULL) c = 1ULL;
            double kld_mean = kld / (double)((size_t)N * (size_t)LAT);
            double ce_mean  = ce / (double)N;
            double pw       = hg / (double)c;
            out[0] = (float)(0.05 * kld_mean + 0.2 * ce_mean + 0.75 * pw);
        }
    }
}

extern "C" void kernel_launch(void* const* d_in, const int* in_sizes, int n_in,
                              void* d_out, int out_size)
{
    const float* m  = (const float*)d_in[0];
    const float* zm = (const float*)d_in[1];
    const float* zs = (const float*)d_in[2];
    const float* o  = (const float*)d_in[3];
    const int*   y  = (const int*)d_in[4];
    const int*   t  = (const int*)d_in[5];
    float* out = (float*)d_out;

    const int N   = in_sizes[5];           // 4096
    const int V   = in_sizes[0] / N;       // 20000
    const int LAT = in_sizes[1] / N;       // 32
    const int L   = L_FIXED;               // 1024
    const int U   = in_sizes[3] / L;       // 128

    const int grid = U + KLD_BLOCKS + NCE_BLOCKS;   // 1160

    init_kernel<<<1, 1>>>(t, N);
    loss_kernel<<<grid, TPB>>>(m, zm, zs, o, y, t, out, N, V, LAT, U, L);
}